// round 11
// baseline (speedup 1.0000x reference)
#include <cuda_runtime.h>
#include <cuda_bf16.h>
#include <math.h>
#include <stdint.h>

// Problem constants
#define VV   32000
#define EE   256
#define DDIM 25
#define BB   64
#define TTOT 24
#define HH   625      // D*D
// xs layout: [0,25) cU | [25,281) word | [281,906) cS | [906,1531) hS | [1531,1556) hU | pad -> 1600
#define KP2  1600     // padded K for gate mma (25 chunks of 64)
#define NR   2624     // padded gate rows (41*64); real gates = 2600
#define GSPLIT 5
#define GSEG   320    // KP2 / GSPLIT = 5 chunks of 64
#define WO_LD  640    // padded H (int8 K: 5 chunks of 128)

// Scratch (device globals; no runtime allocation)
__device__ float d_bias[NR];
__device__ float d_xs[BB * KP2];
__device__ __nv_bfloat16 d_xsHi[BB * KP2];
__device__ __nv_bfloat16 d_xsLo[BB * KP2];
__device__ __nv_bfloat16 d_WcatHi[NR * KP2];
__device__ __nv_bfloat16 d_WcatLo[NR * KP2];
__device__ float d_gpart[GSPLIT * BB * NR];
// int8 FC operands (two-level quantization) + per-row scales
__device__ signed char d_fcQ1[VV * WO_LD];
__device__ signed char d_fcQ2[VV * WO_LD];
__device__ float       d_sbB[VV];
__device__ signed char d_woQ1[TTOT * BB * WO_LD];
__device__ signed char d_woQ2[TTOT * BB * WO_LD];
__device__ float       d_saA[TTOT * BB];

__device__ __forceinline__ float sigm(float x) { return 1.0f / (1.0f + expf(-x)); }

__device__ __forceinline__ void set_xs(int b, int k, float v) {
    d_xs[b * KP2 + k] = v;
    __nv_bfloat16 h = __float2bfloat16(v);
    d_xsHi[b * KP2 + k] = h;
    d_xsLo[b * KP2 + k] = __float2bfloat16(v - __bfloat162float(h));
}

__device__ __forceinline__ uint32_t smem_u32(const void* p) {
    uint32_t a;
    asm("{ .reg .u64 t; cvta.to.shared.u64 t, %1; cvt.u32.u64 %0, t; }" : "=r"(a) : "l"(p));
    return a;
}
#define LDSM4(r0, r1, r2, r3, a) \
    asm volatile("ldmatrix.sync.aligned.m8n8.x4.shared.b16 {%0,%1,%2,%3}, [%4];" \
                 : "=r"(r0), "=r"(r1), "=r"(r2), "=r"(r3) : "r"(a))
#define CP_ASYNC16(dst, src) \
    asm volatile("cp.async.cg.shared.global [%0], [%1], 16;" :: "r"(dst), "l"(src))
#define CP_COMMIT() asm volatile("cp.async.commit_group;" ::: "memory")
#define CP_WAIT(n)  asm volatile("cp.async.wait_group %0;" :: "n"(n) : "memory")

__device__ __forceinline__ void mma_bf16(float* c, const uint32_t* a, const uint32_t* b) {
    asm volatile("mma.sync.aligned.m16n8k16.row.col.f32.bf16.bf16.f32 "
                 "{%0,%1,%2,%3}, {%4,%5,%6,%7}, {%8,%9}, {%0,%1,%2,%3};"
                 : "+f"(c[0]), "+f"(c[1]), "+f"(c[2]), "+f"(c[3])
                 : "r"(a[0]), "r"(a[1]), "r"(a[2]), "r"(a[3]), "r"(b[0]), "r"(b[1]));
}
__device__ __forceinline__ void mma_s8(int* c, const uint32_t* a, const uint32_t* b) {
    asm volatile("mma.sync.aligned.m16n8k32.row.col.s32.s8.s8.s32 "
                 "{%0,%1,%2,%3}, {%4,%5,%6,%7}, {%8,%9}, {%0,%1,%2,%3};"
                 : "+r"(c[0]), "+r"(c[1]), "+r"(c[2]), "+r"(c[3])
                 : "r"(a[0]), "r"(a[1]), "r"(a[2]), "r"(a[3]), "r"(b[0]), "r"(b[1]));
}
__device__ __forceinline__ int q_clamp(float x) {
    int q = __float2int_rn(x);
    return max(-127, min(127, q));
}

// ============================ prep kernels ============================
__global__ void k_prep_wcat(const float* __restrict__ WihS, const float* __restrict__ WhhS,
                            const float* __restrict__ bihS, const float* __restrict__ bhhS,
                            const float* __restrict__ WihU, const float* __restrict__ WhhU,
                            const float* __restrict__ bihU, const float* __restrict__ bhhU) {
    int r = blockIdx.x;
    int tid = threadIdx.x;
    for (int c = tid; c < KP2; c += 256) {
        float v = 0.0f;
        if (r < 2500) {
            if (c < 906)        v = WihS[r * 906 + c];
            else if (c < 1531)  v = WhhS[r * 625 + (c - 906)];
        } else if (r < 2600) {
            int r2 = r - 2500;
            if (c < 906)                    v = WihU[r2 * 906 + c];
            else if (c >= 1531 && c < 1556) v = WhhU[r2 * 25 + (c - 1531)];
        }
        __nv_bfloat16 h = __float2bfloat16(v);
        d_WcatHi[r * KP2 + c] = h;
        d_WcatLo[r * KP2 + c] = __float2bfloat16(v - __bfloat162float(h));
    }
    if (tid == 0) {
        float bv = 0.0f;
        if (r < 2500)       bv = bihS[r] + bhhS[r];
        else if (r < 2600)  bv = bihU[r - 2500] + bhhU[r - 2500];
        d_bias[r] = bv;
    }
}

// fcW [32000 x 625] -> int8 two-level quantized [32000 x 640] + per-row scale
__global__ void k_prep_fcq(const float* __restrict__ fcW) {
    __shared__ float sv[WO_LD];
    __shared__ float sred[256];
    int n = blockIdx.x;
    int tid = threadIdx.x;
    float lm = 0.0f;
    for (int k = tid; k < WO_LD; k += 256) {
        float x = (k < 625) ? fcW[n * 625 + k] : 0.0f;
        sv[k] = x;
        lm = fmaxf(lm, fabsf(x));
    }
    sred[tid] = lm;
    __syncthreads();
    for (int s = 128; s > 0; s >>= 1) {
        if (tid < s) sred[tid] = fmaxf(sred[tid], sred[tid + s]);
        __syncthreads();
    }
    float m = sred[0];
    float sa = m / 127.0f;
    float inv = (m > 0.0f) ? 127.0f / m : 0.0f;
    for (int k = tid; k < WO_LD; k += 256) {
        float x = sv[k];
        int q1 = q_clamp(x * inv);
        float r = x - sa * (float)q1;
        int q2 = q_clamp(r * inv * 128.0f);
        d_fcQ1[n * WO_LD + k] = (signed char)q1;
        d_fcQ2[n * WO_LD + k] = (signed char)q2;
    }
    if (tid == 0) d_sbB[n] = sa;
}

// Zero int8 wordOut q arrays + scales (slice 0 rows + pad cols must be zero)
__global__ void k_zero_wo() {
    int i = blockIdx.x * 256 + threadIdx.x;
    if (i < TTOT * BB * WO_LD) {
        d_woQ1[i] = 0;
        d_woQ2[i] = 0;
    }
    if (i < TTOT * BB) d_saA[i] = 0.0f;
}

__global__ void k_init(const float* __restrict__ features, const float* __restrict__ szW,
                       const float* __restrict__ szb, const float* __restrict__ embed) {
    int b = blockIdx.x;
    int tid = threadIdx.x;
    __shared__ float sf[EE];
    for (int k = tid; k < KP2; k += 256) {
        d_xs[b * KP2 + k] = 0.0f;
        d_xsHi[b * KP2 + k] = __float2bfloat16(0.0f);
        d_xsLo[b * KP2 + k] = __float2bfloat16(0.0f);
    }
    for (int e = tid; e < EE; e += 256) sf[e] = features[b * EE + e];
    __syncthreads();
    for (int e = tid; e < EE; e += 256) set_xs(b, 25 + e, embed[e]);
    for (int j = tid; j < HH; j += 256) {
        float s = szb[j];
        const float* w = szW + j * EE;
        #pragma unroll 8
        for (int e = 0; e < EE; e++) s += sf[e] * w[e];
        set_xs(b, 281 + j, s);
    }
}

// ============================ gate GEMM via mma.sync (unchanged, proven) ============================
#define GALD   72
#define GTILEE (64 * GALD)

__global__ __launch_bounds__(128) void k_gates_mma() {
    __shared__ __nv_bfloat16 sm[4 * GTILEE];   // 36864 B
    int tid = threadIdx.x;
    int wid = tid >> 5;
    int lane = tid & 31;
    int nBase = blockIdx.x * 64;
    int ks = blockIdx.y;
    int k0 = ks * GSEG;

    float acc[4][2][4];
    #pragma unroll
    for (int i = 0; i < 4; i++)
        #pragma unroll
        for (int j = 0; j < 2; j++)
            #pragma unroll
            for (int q = 0; q < 4; q++) acc[i][j][q] = 0.0f;

    uint32_t smb = smem_u32(sm);
    int aRow = (lane & 15), aKoff = (lane >> 4) * 8;
    int bRow = ((lane >> 4) * 8) + (lane & 7), bKoff = ((lane >> 3) & 1) * 8;

    for (int c = 0; c < 5; c++) {
        #pragma unroll
        for (int tsel = 0; tsel < 4; tsel++) {
            const __nv_bfloat16* src =
                (tsel == 0) ? d_xsHi : (tsel == 1) ? d_xsLo : (tsel == 2) ? d_WcatHi : d_WcatLo;
            int rowBase = (tsel < 2) ? 0 : nBase;
            __nv_bfloat16* dst = sm + tsel * GTILEE;
            #pragma unroll
            for (int l = 0; l < 8; l++) {
                int idx = tid + l * 128;
                int r = idx >> 4, q = idx & 15;
                uint2 v = *(const uint2*)(src + (size_t)(rowBase + r) * KP2 + k0 + c * 64 + q * 4);
                *(uint2*)(dst + r * GALD + q * 4) = v;
            }
        }
        __syncthreads();

        #pragma unroll
        for (int kk = 0; kk < 4; kk++) {
            uint32_t ah[4][4], al[4][4], bh[2][2], bl[2][2];
            #pragma unroll
            for (int mi = 0; mi < 4; mi++) {
                uint32_t off = (uint32_t)((mi * 16 + aRow) * GALD + kk * 16 + aKoff) * 2;
                LDSM4(ah[mi][0], ah[mi][1], ah[mi][2], ah[mi][3], smb + off);
                LDSM4(al[mi][0], al[mi][1], al[mi][2], al[mi][3], smb + (uint32_t)(GTILEE * 2) + off);
            }
            {
                uint32_t off = (uint32_t)((wid * 16 + bRow) * GALD + kk * 16 + bKoff) * 2;
                uint32_t r0, r1, r2, r3;
                LDSM4(r0, r1, r2, r3, smb + (uint32_t)(2 * GTILEE * 2) + off);
                bh[0][0] = r0; bh[0][1] = r1; bh[1][0] = r2; bh[1][1] = r3;
                LDSM4(r0, r1, r2, r3, smb + (uint32_t)(3 * GTILEE * 2) + off);
                bl[0][0] = r0; bl[0][1] = r1; bl[1][0] = r2; bl[1][1] = r3;
            }
            #pragma unroll
            for (int mi = 0; mi < 4; mi++)
                #pragma unroll
                for (int ni = 0; ni < 2; ni++) {
                    mma_bf16(acc[mi][ni], ah[mi], bh[ni]);
                    mma_bf16(acc[mi][ni], ah[mi], bl[ni]);
                    mma_bf16(acc[mi][ni], al[mi], bh[ni]);
                }
        }
        __syncthreads();
    }

    float* gp = d_gpart + ks * (BB * NR);
    int g = lane >> 2, tig = lane & 3;
    #pragma unroll
    for (int ni = 0; ni < 2; ni++) {
        int col = nBase + wid * 16 + ni * 8 + 2 * tig;
        #pragma unroll
        for (int mi = 0; mi < 4; mi++) {
            int row0 = mi * 16 + g;
            float2 v0 = { acc[mi][ni][0], acc[mi][ni][1] };
            float2 v1 = { acc[mi][ni][2], acc[mi][ni][3] };
            *(float2*)&gp[(size_t)row0 * NR + col] = v0;
            *(float2*)&gp[(size_t)(row0 + 8) * NR + col] = v1;
        }
    }
}

// ============================ cell update (+ int8 row quantization) ============================
__global__ __launch_bounds__(256) void k_cellft(int t, const int* __restrict__ captions,
                                                const float* __restrict__ embed,
                                                const float* __restrict__ wuW,
                                                const float* __restrict__ wub) {
    int b = blockIdx.x;
    int tid = threadIdx.x;
    __shared__ float shS[HH];
    __shared__ float shU[DDIM];
    __shared__ float sut[HH];
    __shared__ float sft[HH];
    __shared__ float sred[256];

    for (int j = tid; j < 650; j += 256) {
        int gi, st, coff, hoff;
        if (j < 625) { gi = j;                st = 625; coff = 281 + j;   hoff = 906 + j; }
        else         { gi = 2500 + (j - 625); st = 25;  coff = (j - 625); hoff = 1531 + (j - 625); }
        float si = d_bias[gi], sf = d_bias[gi + st], sg = d_bias[gi + 2 * st], so = d_bias[gi + 3 * st];
        #pragma unroll
        for (int s = 0; s < GSPLIT; s++) {
            const float* gp = d_gpart + s * (BB * NR) + b * NR;
            si += gp[gi]; sf += gp[gi + st]; sg += gp[gi + 2 * st]; so += gp[gi + 3 * st];
        }
        float c_old = d_xs[b * KP2 + coff];
        float c = sigm(sf) * c_old + sigm(si) * tanhf(sg);
        float h = sigm(so) * tanhf(c);
        set_xs(b, coff, c);
        set_xs(b, hoff, h);
        if (j < 625) shS[j] = h; else shU[j - 625] = h;
    }
    __syncthreads();
    for (int j = tid; j < HH; j += 256) {
        float s = wub[j];
        const float* w = wuW + j * DDIM;
        #pragma unroll
        for (int e = 0; e < DDIM; e++) s += shU[e] * w[e];
        sut[j] = s;
    }
    __syncthreads();
    float lm = 0.0f;
    for (int j = tid; j < HH; j += 256) {
        int r = j / DDIM, c = j % DDIM;
        float s = 0.0f;
        #pragma unroll
        for (int m = 0; m < DDIM; m++) s += sut[r * DDIM + m] * shS[m * DDIM + c];
        sft[j] = s;
        lm = fmaxf(lm, fabsf(s));
    }
    sred[tid] = lm;
    __syncthreads();
    for (int s = 128; s > 0; s >>= 1) {
        if (tid < s) sred[tid] = fmaxf(sred[tid], sred[tid + s]);
        __syncthreads();
    }
    float m = sred[0];
    float sa = m / 127.0f;
    float inv = (m > 0.0f) ? 127.0f / m : 0.0f;
    int row = (t + 1) * BB + b;
    for (int j = tid; j < HH; j += 256) {
        float x = sft[j];
        int q1 = q_clamp(x * inv);
        float r = x - sa * (float)q1;
        int q2 = q_clamp(r * inv * 128.0f);
        d_woQ1[(size_t)row * WO_LD + j] = (signed char)q1;
        d_woQ2[(size_t)row * WO_LD + j] = (signed char)q2;
    }
    if (tid == 0) d_saA[row] = sa;
    if (t + 1 <= 22) {
        int w = captions[b * TTOT + (t + 1)];
        for (int e = tid; e < EE; e += 256)
            set_xs(b, 25 + e, embed[w * EE + e]);
    }
}

// ============================ int8 IMMA FC GEMM ============================
// out[1536 x 32000] = sa[m]*sb[n]*(D11 + (D12+D21)/128) + fcb[n]
// CTA 128(M) x 128(N), K = 640 int8 in 5 chunks of 128B. cp.async double buffer.
// 1 CTA/SM (regs), warp tile 64x32, mma.sync.m16n8k32.s8.
#define NCH8   5
#define QLD    144                          // byte row stride (16B-aligned, odd 16B-units)
#define QTILEB (128 * QLD)                  // 18432 B per tile
#define QSTAGE (4 * QTILEB)                 // Aq1, Aq2, Bq1, Bq2
#define FC_SMEM8 (2 * QSTAGE)               // 147456 B

__global__ __launch_bounds__(256) void k_fc_imma(const float* __restrict__ fcb, float* __restrict__ out) {
    extern __shared__ signed char sm8[];

    int tid = threadIdx.x;
    int wid = tid >> 5;
    int lane = tid & 31;
    int wm = wid & 1;          // 0..1 (M)
    int wn = wid >> 1;         // 0..3 (N)
    int mBase = blockIdx.x * 128;   // 12 (fast dim -> B reuse in L2)
    int nBase = blockIdx.y * 128;   // 250

    uint32_t smb = smem_u32(sm8);

    auto load_chunk = [&](int c, int stage) {
        #pragma unroll
        for (int tsel = 0; tsel < 4; tsel++) {
            const signed char* src =
                (tsel == 0) ? d_woQ1 : (tsel == 1) ? d_woQ2 : (tsel == 2) ? d_fcQ1 : d_fcQ2;
            int rowBase = (tsel < 2) ? mBase : nBase;
            uint32_t dstBase = smb + (uint32_t)(stage * QSTAGE + tsel * QTILEB);
            #pragma unroll
            for (int l = 0; l < 4; l++) {
                int idx = tid + l * 256;       // 1024 x 16B per tile (128 rows x 8)
                int r = idx >> 3, q = idx & 7;
                const signed char* s = src + (size_t)(rowBase + r) * WO_LD + c * 128 + q * 16;
                CP_ASYNC16(dstBase + (uint32_t)(r * QLD + q * 16), s);
            }
        }
        CP_COMMIT();
    };

    int acc1[4][4][4];   // q1*q1
    int accx[4][4][4];   // q1*q2 + q2*q1
    #pragma unroll
    for (int i = 0; i < 4; i++)
        #pragma unroll
        for (int j = 0; j < 4; j++)
            #pragma unroll
            for (int q = 0; q < 4; q++) { acc1[i][j][q] = 0; accx[i][j][q] = 0; }

    // s8 k32 fragment addressing (bytes); same ldmatrix pattern as bf16 k16,
    // with 16B granules now spanning 16 int8 K-positions.
    int aRow = (lane & 15);
    int aKoffB = (lane >> 4) * 16;
    int bRow = ((lane >> 4) * 8) + (lane & 7);
    int bKoffB = ((lane >> 3) & 1) * 16;

    load_chunk(0, 0);

    for (int c = 0; c < NCH8; c++) {
        if (c + 1 < NCH8) {
            load_chunk(c + 1, (c + 1) & 1);
            CP_WAIT(1);
        } else {
            CP_WAIT(0);
        }
        __syncthreads();

        uint32_t stBase = (uint32_t)((c & 1) * QSTAGE);
        #pragma unroll
        for (int kk = 0; kk < 4; kk++) {       // 4 x k32 = 128 int8 K per chunk
            uint32_t a1[4][4], a2[4][4], b1[4][2], b2[4][2];
            #pragma unroll
            for (int mi = 0; mi < 4; mi++) {
                uint32_t off = stBase + (uint32_t)((wm * 64 + mi * 16 + aRow) * QLD + kk * 32 + aKoffB);
                LDSM4(a1[mi][0], a1[mi][1], a1[mi][2], a1[mi][3], smb + off);
                LDSM4(a2[mi][0], a2[mi][1], a2[mi][2], a2[mi][3], smb + (uint32_t)QTILEB + off);
            }
            #pragma unroll
            for (int j = 0; j < 2; j++) {
                uint32_t off = stBase + (uint32_t)((wn * 32 + j * 16 + bRow) * QLD + kk * 32 + bKoffB);
                uint32_t r0, r1, r2, r3;
                LDSM4(r0, r1, r2, r3, smb + (uint32_t)(2 * QTILEB) + off);
                b1[2 * j][0] = r0; b1[2 * j][1] = r1; b1[2 * j + 1][0] = r2; b1[2 * j + 1][1] = r3;
                LDSM4(r0, r1, r2, r3, smb + (uint32_t)(3 * QTILEB) + off);
                b2[2 * j][0] = r0; b2[2 * j][1] = r1; b2[2 * j + 1][0] = r2; b2[2 * j + 1][1] = r3;
            }
            #pragma unroll
            for (int mi = 0; mi < 4; mi++)
                #pragma unroll
                for (int ni = 0; ni < 4; ni++) {
                    mma_s8(acc1[mi][ni], a1[mi], b1[ni]);
                    mma_s8(accx[mi][ni], a1[mi], b2[ni]);
                    mma_s8(accx[mi][ni], a2[mi], b1[ni]);
                }
        }
        __syncthreads();
    }

    int g = lane >> 2, tig = lane & 3;
    #pragma unroll
    for (int ni = 0; ni < 4; ni++) {
        int col = nBase + wn * 32 + ni * 8 + 2 * tig;
        float sb0 = d_sbB[col], sb1 = d_sbB[col + 1];
        float fb0 = fcb[col], fb1 = fcb[col + 1];
        #pragma unroll
        for (int mi = 0; mi < 4; mi++) {
            int row0 = mBase + wm * 64 + mi * 16 + g;
            float sa0 = d_saA[row0], sa1 = d_saA[row0 + 8];
            float2 v0, v1;
            v0.x = sa0 * sb0 * ((float)acc1[mi][ni][0] + 0.0078125f * (float)accx[mi][ni][0]) + fb0;
            v0.y = sa0 * sb1 * ((float)acc1[mi][ni][1] + 0.0078125f * (float)accx[mi][ni][1]) + fb1;
            v1.x = sa1 * sb0 * ((float)acc1[mi][ni][2] + 0.0078125f * (float)accx[mi][ni][2]) + fb0;
            v1.y = sa1 * sb1 * ((float)acc1[mi][ni][3] + 0.0078125f * (float)accx[mi][ni][3]) + fb1;
            *(float2*)&out[(size_t)row0 * VV + col] = v0;
            *(float2*)&out[(size_t)(row0 + 8) * VV + col] = v1;
        }
    }
}

// ---------------------------------------------------------------------------
extern "C" void kernel_launch(void* const* d_in, const int* in_sizes, int n_in,
                              void* d_out, int out_size) {
    const float* features = (const float*)d_in[0];
    const int*   captions = (const int*)  d_in[1];
    const float* embed    = (const float*)d_in[2];
    const float* WihS     = (const float*)d_in[3];
    const float* WhhS     = (const float*)d_in[4];
    const float* bihS     = (const float*)d_in[5];
    const float* bhhS     = (const float*)d_in[6];
    const float* WihU     = (const float*)d_in[7];
    const float* WhhU     = (const float*)d_in[8];
    const float* bihU     = (const float*)d_in[9];
    const float* bhhU     = (const float*)d_in[10];
    const float* fcW      = (const float*)d_in[11];
    const float* fcb      = (const float*)d_in[12];
    const float* szW      = (const float*)d_in[13];
    const float* szb      = (const float*)d_in[14];
    const float* wuW      = (const float*)d_in[15];
    const float* wub      = (const float*)d_in[16];
    float* out = (float*)d_out;

    cudaFuncSetAttribute(k_fc_imma, cudaFuncAttributeMaxDynamicSharedMemorySize, FC_SMEM8);

    k_prep_wcat<<<NR, 256>>>(WihS, WhhS, bihS, bhhS, WihU, WhhU, bihU, bhhU);
    k_prep_fcq<<<VV, 256>>>(fcW);
    k_init<<<BB, 256>>>(features, szW, szb, embed);
    k_zero_wo<<<(TTOT * BB * WO_LD + 255) / 256, 256>>>();

    for (int t = 0; t < 23; t++) {
        k_gates_mma<<<dim3(41, GSPLIT), 128>>>();
        k_cellft<<<BB, 256>>>(t, captions, embed, wuW, wub);
    }

    k_fc_imma<<<dim3(12, 250), 256, FC_SMEM8>>>(fcb, out);
}

// round 12
// speedup vs baseline: 1.7820x; 1.7820x over previous
#include <cuda_runtime.h>
#include <cuda_bf16.h>
#include <math.h>
#include <stdint.h>

// Problem constants
#define VV   32000
#define EE   256
#define DDIM 25
#define BB   64
#define TTOT 24
#define HH   625      // D*D
// xs layout: [0,25) cU | [25,281) word | [281,906) cS | [906,1531) hS | [1531,1556) hU | pad -> 1600
#define KP2  1600     // padded K for gate mma (25 chunks of 64)
#define NR   2624     // padded gate rows (41*64); real gates = 2600
#define GSPLIT 5
#define GSEG   320    // KP2 / GSPLIT = 5 chunks of 64
#define WO_LD  640    // padded H for FC GEMM

// Scratch (device globals; no runtime allocation)
__device__ float d_bias[NR];
__device__ float d_xs[BB * KP2];
__device__ __nv_bfloat16 d_xsHi[BB * KP2];
__device__ __nv_bfloat16 d_xsLo[BB * KP2];
__device__ __nv_bfloat16 d_WcatHi[NR * KP2];
__device__ __nv_bfloat16 d_WcatLo[NR * KP2];
__device__ float d_gpart[GSPLIT * BB * NR];
__device__ __nv_bfloat16 d_fcHi[VV * WO_LD];
__device__ __nv_bfloat16 d_fcLo[VV * WO_LD];
__device__ __nv_bfloat16 d_woHi[TTOT * BB * WO_LD];
__device__ __nv_bfloat16 d_woLo[TTOT * BB * WO_LD];

__device__ __forceinline__ float sigm(float x) { return 1.0f / (1.0f + expf(-x)); }

__device__ __forceinline__ void set_xs(int b, int k, float v) {
    d_xs[b * KP2 + k] = v;
    __nv_bfloat16 h = __float2bfloat16(v);
    d_xsHi[b * KP2 + k] = h;
    d_xsLo[b * KP2 + k] = __float2bfloat16(v - __bfloat162float(h));
}

__device__ __forceinline__ uint32_t smem_u32(const void* p) {
    uint32_t a;
    asm("{ .reg .u64 t; cvta.to.shared.u64 t, %1; cvt.u32.u64 %0, t; }" : "=r"(a) : "l"(p));
    return a;
}
#define LDSM4(r0, r1, r2, r3, a) \
    asm volatile("ldmatrix.sync.aligned.m8n8.x4.shared.b16 {%0,%1,%2,%3}, [%4];" \
                 : "=r"(r0), "=r"(r1), "=r"(r2), "=r"(r3) : "r"(a))
#define CP_ASYNC16(dst, src) \
    asm volatile("cp.async.cg.shared.global [%0], [%1], 16;" :: "r"(dst), "l"(src))
#define CP_COMMIT() asm volatile("cp.async.commit_group;" ::: "memory")
#define CP_WAIT(n)  asm volatile("cp.async.wait_group %0;" :: "n"(n) : "memory")

__device__ __forceinline__ void mma_bf16(float* c, const uint32_t* a, const uint32_t* b) {
    asm volatile("mma.sync.aligned.m16n8k16.row.col.f32.bf16.bf16.f32 "
                 "{%0,%1,%2,%3}, {%4,%5,%6,%7}, {%8,%9}, {%0,%1,%2,%3};"
                 : "+f"(c[0]), "+f"(c[1]), "+f"(c[2]), "+f"(c[3])
                 : "r"(a[0]), "r"(a[1]), "r"(a[2]), "r"(a[3]), "r"(b[0]), "r"(b[1]));
}

// ============================ prep kernels ============================
__global__ void k_prep_wcat(const float* __restrict__ WihS, const float* __restrict__ WhhS,
                            const float* __restrict__ bihS, const float* __restrict__ bhhS,
                            const float* __restrict__ WihU, const float* __restrict__ WhhU,
                            const float* __restrict__ bihU, const float* __restrict__ bhhU) {
    int r = blockIdx.x;
    int tid = threadIdx.x;
    for (int c = tid; c < KP2; c += 256) {
        float v = 0.0f;
        if (r < 2500) {
            if (c < 906)        v = WihS[r * 906 + c];
            else if (c < 1531)  v = WhhS[r * 625 + (c - 906)];
        } else if (r < 2600) {
            int r2 = r - 2500;
            if (c < 906)                    v = WihU[r2 * 906 + c];
            else if (c >= 1531 && c < 1556) v = WhhU[r2 * 25 + (c - 1531)];
        }
        __nv_bfloat16 h = __float2bfloat16(v);
        d_WcatHi[r * KP2 + c] = h;
        d_WcatLo[r * KP2 + c] = __float2bfloat16(v - __bfloat162float(h));
    }
    if (tid == 0) {
        float bv = 0.0f;
        if (r < 2500)       bv = bihS[r] + bhhS[r];
        else if (r < 2600)  bv = bihU[r - 2500] + bhhU[r - 2500];
        d_bias[r] = bv;
    }
}

__global__ void k_prep_fcw(const float* __restrict__ fcW) {
    int n = blockIdx.x;
    int tid = threadIdx.x;
    for (int k = tid; k < WO_LD; k += 256) {
        float x = (k < 625) ? fcW[n * 625 + k] : 0.0f;
        __nv_bfloat16 h = __float2bfloat16(x);
        __nv_bfloat16 l = __float2bfloat16(x - __bfloat162float(h));
        d_fcHi[n * WO_LD + k] = h;
        d_fcLo[n * WO_LD + k] = l;
    }
}

// Zero bf16 wordOut hi/lo (slice 0 + pad cols must be zero)
__global__ void k_zero_wo() {
    int i = blockIdx.x * 256 + threadIdx.x;
    if (i < TTOT * BB * WO_LD) {
        d_woHi[i] = __float2bfloat16(0.0f);
        d_woLo[i] = __float2bfloat16(0.0f);
    }
}

__global__ void k_init(const float* __restrict__ features, const float* __restrict__ szW,
                       const float* __restrict__ szb, const float* __restrict__ embed) {
    int b = blockIdx.x;
    int tid = threadIdx.x;
    __shared__ float sf[EE];
    for (int k = tid; k < KP2; k += 256) {
        d_xs[b * KP2 + k] = 0.0f;
        d_xsHi[b * KP2 + k] = __float2bfloat16(0.0f);
        d_xsLo[b * KP2 + k] = __float2bfloat16(0.0f);
    }
    for (int e = tid; e < EE; e += 256) sf[e] = features[b * EE + e];
    __syncthreads();
    for (int e = tid; e < EE; e += 256) set_xs(b, 25 + e, embed[e]);
    for (int j = tid; j < HH; j += 256) {
        float s = szb[j];
        const float* w = szW + j * EE;
        #pragma unroll 8
        for (int e = 0; e < EE; e++) s += sf[e] * w[e];
        set_xs(b, 281 + j, s);
    }
}

// ============================ gate GEMM via mma.sync (R7-proven) ============================
#define GALD   72
#define GTILEE (64 * GALD)

__global__ __launch_bounds__(128) void k_gates_mma() {
    __shared__ __nv_bfloat16 sm[4 * GTILEE];   // 36864 B
    int tid = threadIdx.x;
    int wid = tid >> 5;
    int lane = tid & 31;
    int nBase = blockIdx.x * 64;
    int ks = blockIdx.y;
    int k0 = ks * GSEG;

    float acc[4][2][4];
    #pragma unroll
    for (int i = 0; i < 4; i++)
        #pragma unroll
        for (int j = 0; j < 2; j++)
            #pragma unroll
            for (int q = 0; q < 4; q++) acc[i][j][q] = 0.0f;

    uint32_t smb = smem_u32(sm);
    int aRow = (lane & 15), aKoff = (lane >> 4) * 8;
    int bRow = ((lane >> 4) * 8) + (lane & 7), bKoff = ((lane >> 3) & 1) * 8;

    for (int c = 0; c < 5; c++) {
        #pragma unroll
        for (int tsel = 0; tsel < 4; tsel++) {
            const __nv_bfloat16* src =
                (tsel == 0) ? d_xsHi : (tsel == 1) ? d_xsLo : (tsel == 2) ? d_WcatHi : d_WcatLo;
            int rowBase = (tsel < 2) ? 0 : nBase;
            __nv_bfloat16* dst = sm + tsel * GTILEE;
            #pragma unroll
            for (int l = 0; l < 8; l++) {
                int idx = tid + l * 128;
                int r = idx >> 4, q = idx & 15;
                uint2 v = *(const uint2*)(src + (size_t)(rowBase + r) * KP2 + k0 + c * 64 + q * 4);
                *(uint2*)(dst + r * GALD + q * 4) = v;
            }
        }
        __syncthreads();

        #pragma unroll
        for (int kk = 0; kk < 4; kk++) {
            uint32_t ah[4][4], al[4][4], bh[2][2], bl[2][2];
            #pragma unroll
            for (int mi = 0; mi < 4; mi++) {
                uint32_t off = (uint32_t)((mi * 16 + aRow) * GALD + kk * 16 + aKoff) * 2;
                LDSM4(ah[mi][0], ah[mi][1], ah[mi][2], ah[mi][3], smb + off);
                LDSM4(al[mi][0], al[mi][1], al[mi][2], al[mi][3], smb + (uint32_t)(GTILEE * 2) + off);
            }
            {
                uint32_t off = (uint32_t)((wid * 16 + bRow) * GALD + kk * 16 + bKoff) * 2;
                uint32_t r0, r1, r2, r3;
                LDSM4(r0, r1, r2, r3, smb + (uint32_t)(2 * GTILEE * 2) + off);
                bh[0][0] = r0; bh[0][1] = r1; bh[1][0] = r2; bh[1][1] = r3;
                LDSM4(r0, r1, r2, r3, smb + (uint32_t)(3 * GTILEE * 2) + off);
                bl[0][0] = r0; bl[0][1] = r1; bl[1][0] = r2; bl[1][1] = r3;
            }
            #pragma unroll
            for (int mi = 0; mi < 4; mi++)
                #pragma unroll
                for (int ni = 0; ni < 2; ni++) {
                    mma_bf16(acc[mi][ni], ah[mi], bh[ni]);
                    mma_bf16(acc[mi][ni], ah[mi], bl[ni]);
                    mma_bf16(acc[mi][ni], al[mi], bh[ni]);
                }
        }
        __syncthreads();
    }

    float* gp = d_gpart + ks * (BB * NR);
    int g = lane >> 2, tig = lane & 3;
    #pragma unroll
    for (int ni = 0; ni < 2; ni++) {
        int col = nBase + wid * 16 + ni * 8 + 2 * tig;
        #pragma unroll
        for (int mi = 0; mi < 4; mi++) {
            int row0 = mi * 16 + g;
            float2 v0 = { acc[mi][ni][0], acc[mi][ni][1] };
            float2 v1 = { acc[mi][ni][2], acc[mi][ni][3] };
            *(float2*)&gp[(size_t)row0 * NR + col] = v0;
            *(float2*)&gp[(size_t)(row0 + 8) * NR + col] = v1;
        }
    }
}

// ============================ cell update (R7-proven) ============================
__global__ __launch_bounds__(256) void k_cellft(int t, const int* __restrict__ captions,
                                                const float* __restrict__ embed,
                                                const float* __restrict__ wuW,
                                                const float* __restrict__ wub) {
    int b = blockIdx.x;
    int tid = threadIdx.x;
    __shared__ float shS[HH];
    __shared__ float shU[DDIM];
    __shared__ float sut[HH];

    for (int j = tid; j < 650; j += 256) {
        int gi, st, coff, hoff;
        if (j < 625) { gi = j;                st = 625; coff = 281 + j;   hoff = 906 + j; }
        else         { gi = 2500 + (j - 625); st = 25;  coff = (j - 625); hoff = 1531 + (j - 625); }
        float si = d_bias[gi], sf = d_bias[gi + st], sg = d_bias[gi + 2 * st], so = d_bias[gi + 3 * st];
        #pragma unroll
        for (int s = 0; s < GSPLIT; s++) {
            const float* gp = d_gpart + s * (BB * NR) + b * NR;
            si += gp[gi]; sf += gp[gi + st]; sg += gp[gi + 2 * st]; so += gp[gi + 3 * st];
        }
        float c_old = d_xs[b * KP2 + coff];
        float c = sigm(sf) * c_old + sigm(si) * tanhf(sg);
        float h = sigm(so) * tanhf(c);
        set_xs(b, coff, c);
        set_xs(b, hoff, h);
        if (j < 625) shS[j] = h; else shU[j - 625] = h;
    }
    __syncthreads();
    for (int j = tid; j < HH; j += 256) {
        float s = wub[j];
        const float* w = wuW + j * DDIM;
        #pragma unroll
        for (int e = 0; e < DDIM; e++) s += shU[e] * w[e];
        sut[j] = s;
    }
    __syncthreads();
    for (int j = tid; j < HH; j += 256) {
        int r = j / DDIM, c = j % DDIM;
        float s = 0.0f;
        #pragma unroll
        for (int m = 0; m < DDIM; m++) s += sut[r * DDIM + m] * shS[m * DDIM + c];
        size_t oi = (size_t)(t + 1) * (BB * WO_LD) + (size_t)b * WO_LD + j;
        __nv_bfloat16 h = __float2bfloat16(s);
        d_woHi[oi] = h;
        d_woLo[oi] = __float2bfloat16(s - __bfloat162float(h));
    }
    if (t + 1 <= 22) {
        int w = captions[b * TTOT + (t + 1)];
        for (int e = tid; e < EE; e += 256)
            set_xs(b, 25 + e, embed[w * EE + e]);
    }
}

// ============================ pipelined FC GEMM, occupancy-preserving ============================
// out[1536 x 32000] = wordOut @ fcW.T + fcb, bf16x3 HMMA.
// CTA 128x128. K = 640 in 20 chunks of 32 bf16. cp.async double buffer:
// stage = 4 tiles x 128 rows x 40 elem (80B rows, odd 16B-granule stride).
// 2 stages = 81920 B < 114 KB -> 2 CTAs/SM retained.
#define NCHUNK 20
#define CH_K   32
#define ALD    40                          // padded row stride in bf16 (80 B)
#define TILEE  (128 * ALD)                 // 5120 elements = 10240 B
#define FSTAGE (4 * TILEE)                 // Ah, Al, Bh, Bl
#define FC_SMEM (2 * FSTAGE * 2)           // 81920 bytes

__global__ __launch_bounds__(256) void k_fc_mma(const float* __restrict__ fcb, float* __restrict__ out) {
    extern __shared__ __nv_bfloat16 sm[];

    int tid = threadIdx.x;
    int wid = tid >> 5;
    int lane = tid & 31;
    int wm = wid & 1;
    int wn = wid >> 1;
    int mBase = blockIdx.x * 128;   // 12 (fast dim -> B tile reuse in L2)
    int nBase = blockIdx.y * 128;   // 250

    uint32_t smb = smem_u32(sm);

    // async-load one K-chunk (4 tiles of 128x32 bf16) into a stage
    auto load_chunk = [&](int c, int stage) {
        #pragma unroll
        for (int tsel = 0; tsel < 4; tsel++) {
            const __nv_bfloat16* src =
                (tsel == 0) ? d_woHi : (tsel == 1) ? d_woLo : (tsel == 2) ? d_fcHi : d_fcLo;
            int rowBase = (tsel < 2) ? mBase : nBase;
            uint32_t dstBase = smb + (uint32_t)(stage * FSTAGE + tsel * TILEE) * 2;
            #pragma unroll
            for (int l = 0; l < 2; l++) {
                int idx = tid + l * 256;       // 512 x 16B per tile (128 rows x 4)
                int r = idx >> 2, q = idx & 3;
                const __nv_bfloat16* s = src + (size_t)(rowBase + r) * WO_LD + c * CH_K + q * 8;
                CP_ASYNC16(dstBase + (uint32_t)(r * 80 + q * 16), s);
            }
        }
        CP_COMMIT();
    };

    float acc[4][4][4];
    #pragma unroll
    for (int i = 0; i < 4; i++)
        #pragma unroll
        for (int j = 0; j < 4; j++)
            #pragma unroll
            for (int q = 0; q < 4; q++) acc[i][j][q] = 0.0f;

    int aRow = (lane & 15), aKoffB = (lane >> 4) * 16;           // bytes
    int bRow = ((lane >> 4) * 8) + (lane & 7), bKoffB = ((lane >> 3) & 1) * 16;

    load_chunk(0, 0);

    for (int c = 0; c < NCHUNK; c++) {
        if (c + 1 < NCHUNK) {
            load_chunk(c + 1, (c + 1) & 1);
            CP_WAIT(1);
        } else {
            CP_WAIT(0);
        }
        __syncthreads();

        uint32_t stBase = (uint32_t)((c & 1) * FSTAGE) * 2;      // bytes
        #pragma unroll
        for (int kk = 0; kk < 2; kk++) {                         // 2 x k16 = 32 per chunk
            uint32_t ah[4][4], al[4][4], bh[4][2], bl[4][2];
            #pragma unroll
            for (int mi = 0; mi < 4; mi++) {
                uint32_t off = stBase + (uint32_t)((wm * 64 + mi * 16 + aRow) * 80 + kk * 32 + aKoffB);
                LDSM4(ah[mi][0], ah[mi][1], ah[mi][2], ah[mi][3], smb + off);
                LDSM4(al[mi][0], al[mi][1], al[mi][2], al[mi][3], smb + (uint32_t)(TILEE * 2) + off);
            }
            #pragma unroll
            for (int j = 0; j < 2; j++) {
                uint32_t off = stBase + (uint32_t)((wn * 32 + j * 16 + bRow) * 80 + kk * 32 + bKoffB);
                uint32_t r0, r1, r2, r3;
                LDSM4(r0, r1, r2, r3, smb + (uint32_t)(2 * TILEE * 2) + off);
                bh[2 * j][0] = r0; bh[2 * j][1] = r1; bh[2 * j + 1][0] = r2; bh[2 * j + 1][1] = r3;
                LDSM4(r0, r1, r2, r3, smb + (uint32_t)(3 * TILEE * 2) + off);
                bl[2 * j][0] = r0; bl[2 * j][1] = r1; bl[2 * j + 1][0] = r2; bl[2 * j + 1][1] = r3;
            }
            #pragma unroll
            for (int mi = 0; mi < 4; mi++)
                #pragma unroll
                for (int ni = 0; ni < 4; ni++) {
                    mma_bf16(acc[mi][ni], ah[mi], bh[ni]);
                    mma_bf16(acc[mi][ni], ah[mi], bl[ni]);
                    mma_bf16(acc[mi][ni], al[mi], bh[ni]);
                }
        }
        __syncthreads();
    }

    int g = lane >> 2, tig = lane & 3;
    #pragma unroll
    for (int ni = 0; ni < 4; ni++) {
        int col = nBase + wn * 32 + ni * 8 + 2 * tig;
        float b0 = fcb[col], b1 = fcb[col + 1];
        #pragma unroll
        for (int mi = 0; mi < 4; mi++) {
            int row0 = mBase + wm * 64 + mi * 16 + g;
            float2 v0 = { acc[mi][ni][0] + b0, acc[mi][ni][1] + b1 };
            float2 v1 = { acc[mi][ni][2] + b0, acc[mi][ni][3] + b1 };
            *(float2*)&out[(size_t)row0 * VV + col] = v0;
            *(float2*)&out[(size_t)(row0 + 8) * VV + col] = v1;
        }
    }
}

// ---------------------------------------------------------------------------
extern "C" void kernel_launch(void* const* d_in, const int* in_sizes, int n_in,
                              void* d_out, int out_size) {
    const float* features = (const float*)d_in[0];
    const int*   captions = (const int*)  d_in[1];
    const float* embed    = (const float*)d_in[2];
    const float* WihS     = (const float*)d_in[3];
    const float* WhhS     = (const float*)d_in[4];
    const float* bihS     = (const float*)d_in[5];
    const float* bhhS     = (const float*)d_in[6];
    const float* WihU     = (const float*)d_in[7];
    const float* WhhU     = (const float*)d_in[8];
    const float* bihU     = (const float*)d_in[9];
    const float* bhhU     = (const float*)d_in[10];
    const float* fcW      = (const float*)d_in[11];
    const float* fcb      = (const float*)d_in[12];
    const float* szW      = (const float*)d_in[13];
    const float* szb      = (const float*)d_in[14];
    const float* wuW      = (const float*)d_in[15];
    const float* wub      = (const float*)d_in[16];
    float* out = (float*)d_out;

    cudaFuncSetAttribute(k_fc_mma, cudaFuncAttributeMaxDynamicSharedMemorySize, FC_SMEM);

    k_prep_wcat<<<NR, 256>>>(WihS, WhhS, bihS, bhhS, WihU, WhhU, bihU, bhhU);
    k_prep_fcw<<<VV, 256>>>(fcW);
    k_init<<<BB, 256>>>(features, szW, szb, embed);
    k_zero_wo<<<(TTOT * BB * WO_LD + 255) / 256, 256>>>();

    for (int t = 0; t < 23; t++) {
        k_gates_mma<<<dim3(41, GSPLIT), 128>>>();
        k_cellft<<<BB, 256>>>(t, captions, embed, wuW, wub);
    }

    k_fc_mma<<<dim3(12, 250), 256, FC_SMEM>>>(fcb, out);
}

// round 13
// speedup vs baseline: 2.0278x; 1.1379x over previous
#include <cuda_runtime.h>
#include <cuda_bf16.h>
#include <cuda_fp16.h>
#include <math.h>
#include <stdint.h>

// Problem constants
#define VV   32000
#define EE   256
#define DDIM 25
#define BB   64
#define TTOT 24
#define HH   625      // D*D
// xs layout: [0,25) cU | [25,281) word | [281,906) cS | [906,1531) hS | [1531,1556) hU | pad -> 1600
#define KP2  1600     // padded K for gate mma (25 chunks of 64)
#define NR   2624     // padded gate rows (41*64); real gates = 2600
#define GSPLIT 5
#define GSEG   320    // KP2 / GSPLIT = 5 chunks of 64
#define WO_LD  640    // padded H for FC GEMM (10 chunks of 64)

// Scratch (device globals; no runtime allocation)
__device__ float d_bias[NR];
__device__ float d_xs[BB * KP2];
__device__ __nv_bfloat16 d_xsHi[BB * KP2];
__device__ __nv_bfloat16 d_xsLo[BB * KP2];
__device__ __nv_bfloat16 d_WcatHi[NR * KP2];
__device__ __nv_bfloat16 d_WcatLo[NR * KP2];
__device__ float d_gpart[GSPLIT * BB * NR];
// fp16 FC operands: A = wordOut two-term (hi+lo), B = fcW single fp16
__device__ __half d_fcH[VV * WO_LD];
__device__ __half d_woHi[TTOT * BB * WO_LD];
__device__ __half d_woLo[TTOT * BB * WO_LD];

__device__ __forceinline__ float sigm(float x) { return 1.0f / (1.0f + expf(-x)); }

__device__ __forceinline__ void set_xs(int b, int k, float v) {
    d_xs[b * KP2 + k] = v;
    __nv_bfloat16 h = __float2bfloat16(v);
    d_xsHi[b * KP2 + k] = h;
    d_xsLo[b * KP2 + k] = __float2bfloat16(v - __bfloat162float(h));
}

__device__ __forceinline__ uint32_t smem_u32(const void* p) {
    uint32_t a;
    asm("{ .reg .u64 t; cvta.to.shared.u64 t, %1; cvt.u32.u64 %0, t; }" : "=r"(a) : "l"(p));
    return a;
}
#define LDSM4(r0, r1, r2, r3, a) \
    asm volatile("ldmatrix.sync.aligned.m8n8.x4.shared.b16 {%0,%1,%2,%3}, [%4];" \
                 : "=r"(r0), "=r"(r1), "=r"(r2), "=r"(r3) : "r"(a))

__device__ __forceinline__ void mma_bf16(float* c, const uint32_t* a, const uint32_t* b) {
    asm volatile("mma.sync.aligned.m16n8k16.row.col.f32.bf16.bf16.f32 "
                 "{%0,%1,%2,%3}, {%4,%5,%6,%7}, {%8,%9}, {%0,%1,%2,%3};"
                 : "+f"(c[0]), "+f"(c[1]), "+f"(c[2]), "+f"(c[3])
                 : "r"(a[0]), "r"(a[1]), "r"(a[2]), "r"(a[3]), "r"(b[0]), "r"(b[1]));
}
__device__ __forceinline__ void mma_f16(float* c, const uint32_t* a, const uint32_t* b) {
    asm volatile("mma.sync.aligned.m16n8k16.row.col.f32.f16.f16.f32 "
                 "{%0,%1,%2,%3}, {%4,%5,%6,%7}, {%8,%9}, {%0,%1,%2,%3};"
                 : "+f"(c[0]), "+f"(c[1]), "+f"(c[2]), "+f"(c[3])
                 : "r"(a[0]), "r"(a[1]), "r"(a[2]), "r"(a[3]), "r"(b[0]), "r"(b[1]));
}

// ============================ prep kernels ============================
__global__ void k_prep_wcat(const float* __restrict__ WihS, const float* __restrict__ WhhS,
                            const float* __restrict__ bihS, const float* __restrict__ bhhS,
                            const float* __restrict__ WihU, const float* __restrict__ WhhU,
                            const float* __restrict__ bihU, const float* __restrict__ bhhU) {
    int r = blockIdx.x;
    int tid = threadIdx.x;
    for (int c = tid; c < KP2; c += 256) {
        float v = 0.0f;
        if (r < 2500) {
            if (c < 906)        v = WihS[r * 906 + c];
            else if (c < 1531)  v = WhhS[r * 625 + (c - 906)];
        } else if (r < 2600) {
            int r2 = r - 2500;
            if (c < 906)                    v = WihU[r2 * 906 + c];
            else if (c >= 1531 && c < 1556) v = WhhU[r2 * 25 + (c - 1531)];
        }
        __nv_bfloat16 h = __float2bfloat16(v);
        d_WcatHi[r * KP2 + c] = h;
        d_WcatLo[r * KP2 + c] = __float2bfloat16(v - __bfloat162float(h));
    }
    if (tid == 0) {
        float bv = 0.0f;
        if (r < 2500)       bv = bihS[r] + bhhS[r];
        else if (r < 2600)  bv = bihU[r - 2500] + bhhU[r - 2500];
        d_bias[r] = bv;
    }
}

// fcW [32000 x 625] -> single fp16 [32000 x 640] (pad zeros)
__global__ void k_prep_fch(const float* __restrict__ fcW) {
    int n = blockIdx.x;
    int tid = threadIdx.x;
    for (int k = tid; k < WO_LD; k += 256) {
        float x = (k < 625) ? fcW[n * 625 + k] : 0.0f;
        d_fcH[n * WO_LD + k] = __float2half_rn(x);
    }
}

// Zero fp16 wordOut hi/lo (slice 0 + pad cols must be zero)
__global__ void k_zero_wo() {
    int i = blockIdx.x * 256 + threadIdx.x;
    if (i < TTOT * BB * WO_LD) {
        d_woHi[i] = __float2half_rn(0.0f);
        d_woLo[i] = __float2half_rn(0.0f);
    }
}

__global__ void k_init(const float* __restrict__ features, const float* __restrict__ szW,
                       const float* __restrict__ szb, const float* __restrict__ embed) {
    int b = blockIdx.x;
    int tid = threadIdx.x;
    __shared__ float sf[EE];
    for (int k = tid; k < KP2; k += 256) {
        d_xs[b * KP2 + k] = 0.0f;
        d_xsHi[b * KP2 + k] = __float2bfloat16(0.0f);
        d_xsLo[b * KP2 + k] = __float2bfloat16(0.0f);
    }
    for (int e = tid; e < EE; e += 256) sf[e] = features[b * EE + e];
    __syncthreads();
    for (int e = tid; e < EE; e += 256) set_xs(b, 25 + e, embed[e]);
    for (int j = tid; j < HH; j += 256) {
        float s = szb[j];
        const float* w = szW + j * EE;
        #pragma unroll 8
        for (int e = 0; e < EE; e++) s += sf[e] * w[e];
        set_xs(b, 281 + j, s);
    }
}

// ============================ gate GEMM via mma.sync (R7-proven, unchanged) ============================
#define GALD   72
#define GTILEE (64 * GALD)

__global__ __launch_bounds__(128) void k_gates_mma() {
    __shared__ __nv_bfloat16 sm[4 * GTILEE];   // 36864 B
    int tid = threadIdx.x;
    int wid = tid >> 5;
    int lane = tid & 31;
    int nBase = blockIdx.x * 64;
    int ks = blockIdx.y;
    int k0 = ks * GSEG;

    float acc[4][2][4];
    #pragma unroll
    for (int i = 0; i < 4; i++)
        #pragma unroll
        for (int j = 0; j < 2; j++)
            #pragma unroll
            for (int q = 0; q < 4; q++) acc[i][j][q] = 0.0f;

    uint32_t smb = smem_u32(sm);
    int aRow = (lane & 15), aKoff = (lane >> 4) * 8;
    int bRow = ((lane >> 4) * 8) + (lane & 7), bKoff = ((lane >> 3) & 1) * 8;

    for (int c = 0; c < 5; c++) {
        #pragma unroll
        for (int tsel = 0; tsel < 4; tsel++) {
            const __nv_bfloat16* src =
                (tsel == 0) ? d_xsHi : (tsel == 1) ? d_xsLo : (tsel == 2) ? d_WcatHi : d_WcatLo;
            int rowBase = (tsel < 2) ? 0 : nBase;
            __nv_bfloat16* dst = sm + tsel * GTILEE;
            #pragma unroll
            for (int l = 0; l < 8; l++) {
                int idx = tid + l * 128;
                int r = idx >> 4, q = idx & 15;
                uint2 v = *(const uint2*)(src + (size_t)(rowBase + r) * KP2 + k0 + c * 64 + q * 4);
                *(uint2*)(dst + r * GALD + q * 4) = v;
            }
        }
        __syncthreads();

        #pragma unroll
        for (int kk = 0; kk < 4; kk++) {
            uint32_t ah[4][4], al[4][4], bh[2][2], bl[2][2];
            #pragma unroll
            for (int mi = 0; mi < 4; mi++) {
                uint32_t off = (uint32_t)((mi * 16 + aRow) * GALD + kk * 16 + aKoff) * 2;
                LDSM4(ah[mi][0], ah[mi][1], ah[mi][2], ah[mi][3], smb + off);
                LDSM4(al[mi][0], al[mi][1], al[mi][2], al[mi][3], smb + (uint32_t)(GTILEE * 2) + off);
            }
            {
                uint32_t off = (uint32_t)((wid * 16 + bRow) * GALD + kk * 16 + bKoff) * 2;
                uint32_t r0, r1, r2, r3;
                LDSM4(r0, r1, r2, r3, smb + (uint32_t)(2 * GTILEE * 2) + off);
                bh[0][0] = r0; bh[0][1] = r1; bh[1][0] = r2; bh[1][1] = r3;
                LDSM4(r0, r1, r2, r3, smb + (uint32_t)(3 * GTILEE * 2) + off);
                bl[0][0] = r0; bl[0][1] = r1; bl[1][0] = r2; bl[1][1] = r3;
            }
            #pragma unroll
            for (int mi = 0; mi < 4; mi++)
                #pragma unroll
                for (int ni = 0; ni < 2; ni++) {
                    mma_bf16(acc[mi][ni], ah[mi], bh[ni]);
                    mma_bf16(acc[mi][ni], ah[mi], bl[ni]);
                    mma_bf16(acc[mi][ni], al[mi], bh[ni]);
                }
        }
        __syncthreads();
    }

    float* gp = d_gpart + ks * (BB * NR);
    int g = lane >> 2, tig = lane & 3;
    #pragma unroll
    for (int ni = 0; ni < 2; ni++) {
        int col = nBase + wid * 16 + ni * 8 + 2 * tig;
        #pragma unroll
        for (int mi = 0; mi < 4; mi++) {
            int row0 = mi * 16 + g;
            float2 v0 = { acc[mi][ni][0], acc[mi][ni][1] };
            float2 v1 = { acc[mi][ni][2], acc[mi][ni][3] };
            *(float2*)&gp[(size_t)row0 * NR + col] = v0;
            *(float2*)&gp[(size_t)(row0 + 8) * NR + col] = v1;
        }
    }
}

// ============================ cell update (fp16 wordOut output) ============================
__global__ __launch_bounds__(256) void k_cellft(int t, const int* __restrict__ captions,
                                                const float* __restrict__ embed,
                                                const float* __restrict__ wuW,
                                                const float* __restrict__ wub) {
    int b = blockIdx.x;
    int tid = threadIdx.x;
    __shared__ float shS[HH];
    __shared__ float shU[DDIM];
    __shared__ float sut[HH];

    for (int j = tid; j < 650; j += 256) {
        int gi, st, coff, hoff;
        if (j < 625) { gi = j;                st = 625; coff = 281 + j;   hoff = 906 + j; }
        else         { gi = 2500 + (j - 625); st = 25;  coff = (j - 625); hoff = 1531 + (j - 625); }
        float si = d_bias[gi], sf = d_bias[gi + st], sg = d_bias[gi + 2 * st], so = d_bias[gi + 3 * st];
        #pragma unroll
        for (int s = 0; s < GSPLIT; s++) {
            const float* gp = d_gpart + s * (BB * NR) + b * NR;
            si += gp[gi]; sf += gp[gi + st]; sg += gp[gi + 2 * st]; so += gp[gi + 3 * st];
        }
        float c_old = d_xs[b * KP2 + coff];
        float c = sigm(sf) * c_old + sigm(si) * tanhf(sg);
        float h = sigm(so) * tanhf(c);
        set_xs(b, coff, c);
        set_xs(b, hoff, h);
        if (j < 625) shS[j] = h; else shU[j - 625] = h;
    }
    __syncthreads();
    for (int j = tid; j < HH; j += 256) {
        float s = wub[j];
        const float* w = wuW + j * DDIM;
        #pragma unroll
        for (int e = 0; e < DDIM; e++) s += shU[e] * w[e];
        sut[j] = s;
    }
    __syncthreads();
    for (int j = tid; j < HH; j += 256) {
        int r = j / DDIM, c = j % DDIM;
        float s = 0.0f;
        #pragma unroll
        for (int m = 0; m < DDIM; m++) s += sut[r * DDIM + m] * shS[m * DDIM + c];
        size_t oi = (size_t)(t + 1) * (BB * WO_LD) + (size_t)b * WO_LD + j;
        __half h = __float2half_rn(s);
        d_woHi[oi] = h;
        d_woLo[oi] = __float2half_rn(s - __half2float(h));
    }
    if (t + 1 <= 22) {
        int w = captions[b * TTOT + (t + 1)];
        for (int e = tid; e < EE; e += 256)
            set_xs(b, 25 + e, embed[w * EE + e]);
    }
}

// ============================ fp16 two-term FC GEMM ============================
// out[1536 x 32000] = (woHi + woLo) @ fcH.T + fcb  via HMMA f16, fp32 accum.
// CTA 128x128, K = 640 in 10 chunks of 64, single-buffered (R7 schedule),
// 3 smem tiles (Ah, Al, B) = 55296 B -> 2 CTAs/SM.
#define NCHUNK 10
#define ALD    72
#define TILEE  (128 * ALD)
#define FC_SMEM (3 * TILEE * 2)        // 55296 bytes

__global__ __launch_bounds__(256) void k_fc_mma(const float* __restrict__ fcb, float* __restrict__ out) {
    extern __shared__ __half sm[];

    int tid = threadIdx.x;
    int wid = tid >> 5;
    int lane = tid & 31;
    int wm = wid & 1;
    int wn = wid >> 1;
    int mBase = blockIdx.x * 128;   // 12 (fast dim -> B tile reuse in L2)
    int nBase = blockIdx.y * 128;   // 250

    float acc[4][4][4];
    #pragma unroll
    for (int i = 0; i < 4; i++)
        #pragma unroll
        for (int j = 0; j < 4; j++)
            #pragma unroll
            for (int q = 0; q < 4; q++) acc[i][j][q] = 0.0f;

    uint32_t smb = smem_u32(sm);
    int aRow = (lane & 15), aKoff = (lane >> 4) * 8;
    int bRow = ((lane >> 4) * 8) + (lane & 7), bKoff = ((lane >> 3) & 1) * 8;

    for (int c = 0; c < NCHUNK; c++) {
        #pragma unroll
        for (int tsel = 0; tsel < 3; tsel++) {
            const __half* src = (tsel == 0) ? d_woHi : (tsel == 1) ? d_woLo : d_fcH;
            int rowBase = (tsel < 2) ? mBase : nBase;
            __half* dst = sm + tsel * TILEE;
            #pragma unroll
            for (int l = 0; l < 8; l++) {
                int idx = tid + l * 256;
                int r = idx >> 4, q = idx & 15;
                uint2 v = *(const uint2*)(src + (size_t)(rowBase + r) * WO_LD + c * 64 + q * 4);
                *(uint2*)(dst + r * ALD + q * 4) = v;
            }
        }
        __syncthreads();

        #pragma unroll
        for (int kk = 0; kk < 4; kk++) {
            uint32_t ah[4][4], al[4][4], bb[4][2];
            #pragma unroll
            for (int mi = 0; mi < 4; mi++) {
                uint32_t off = (uint32_t)((wm * 64 + mi * 16 + aRow) * ALD + kk * 16 + aKoff) * 2;
                LDSM4(ah[mi][0], ah[mi][1], ah[mi][2], ah[mi][3], smb + off);
                LDSM4(al[mi][0], al[mi][1], al[mi][2], al[mi][3], smb + (uint32_t)(TILEE * 2) + off);
            }
            #pragma unroll
            for (int j = 0; j < 2; j++) {
                uint32_t off = (uint32_t)((wn * 32 + j * 16 + bRow) * ALD + kk * 16 + bKoff) * 2;
                uint32_t r0, r1, r2, r3;
                LDSM4(r0, r1, r2, r3, smb + (uint32_t)(2 * TILEE * 2) + off);
                bb[2 * j][0] = r0; bb[2 * j][1] = r1; bb[2 * j + 1][0] = r2; bb[2 * j + 1][1] = r3;
            }
            #pragma unroll
            for (int mi = 0; mi < 4; mi++)
                #pragma unroll
                for (int ni = 0; ni < 4; ni++) {
                    mma_f16(acc[mi][ni], ah[mi], bb[ni]);
                    mma_f16(acc[mi][ni], al[mi], bb[ni]);
                }
        }
        __syncthreads();
    }

    int g = lane >> 2, tig = lane & 3;
    #pragma unroll
    for (int ni = 0; ni < 4; ni++) {
        int col = nBase + wn * 32 + ni * 8 + 2 * tig;
        float b0 = fcb[col], b1 = fcb[col + 1];
        #pragma unroll
        for (int mi = 0; mi < 4; mi++) {
            int row0 = mBase + wm * 64 + mi * 16 + g;
            float2 v0 = { acc[mi][ni][0] + b0, acc[mi][ni][1] + b1 };
            float2 v1 = { acc[mi][ni][2] + b0, acc[mi][ni][3] + b1 };
            *(float2*)&out[(size_t)row0 * VV + col] = v0;
            *(float2*)&out[(size_t)(row0 + 8) * VV + col] = v1;
        }
    }
}

// ---------------------------------------------------------------------------
extern "C" void kernel_launch(void* const* d_in, const int* in_sizes, int n_in,
                              void* d_out, int out_size) {
    const float* features = (const float*)d_in[0];
    const int*   captions = (const int*)  d_in[1];
    const float* embed    = (const float*)d_in[2];
    const float* WihS     = (const float*)d_in[3];
    const float* WhhS     = (const float*)d_in[4];
    const float* bihS     = (const float*)d_in[5];
    const float* bhhS     = (const float*)d_in[6];
    const float* WihU     = (const float*)d_in[7];
    const float* WhhU     = (const float*)d_in[8];
    const float* bihU     = (const float*)d_in[9];
    const float* bhhU     = (const float*)d_in[10];
    const float* fcW      = (const float*)d_in[11];
    const float* fcb      = (const float*)d_in[12];
    const float* szW      = (const float*)d_in[13];
    const float* szb      = (const float*)d_in[14];
    const float* wuW      = (const float*)d_in[15];
    const float* wub      = (const float*)d_in[16];
    float* out = (float*)d_out;

    cudaFuncSetAttribute(k_fc_mma, cudaFuncAttributeMaxDynamicSharedMemorySize, FC_SMEM);

    k_prep_wcat<<<NR, 256>>>(WihS, WhhS, bihS, bhhS, WihU, WhhU, bihU, bhhU);
    k_prep_fch<<<VV, 256>>>(fcW);
    k_init<<<BB, 256>>>(features, szW, szb, embed);
    k_zero_wo<<<(TTOT * BB * WO_LD + 255) / 256, 256>>>();

    for (int t = 0; t < 23; t++) {
        k_gates_mma<<<dim3(41, GSPLIT), 128>>>();
        k_cellft<<<BB, 256>>>(t, captions, embed, wuW, wub);
    }

    k_fc_mma<<<dim3(12, 250), 256, FC_SMEM>>>(fcb, out);
}